// round 3
// baseline (speedup 1.0000x reference)
#include <cuda_runtime.h>
#include <cuda_fp16.h>
#include <cstdint>

// ---------------------------------------------------------------------------
// Problem constants
// ---------------------------------------------------------------------------
#define SIG_LEN     262144
#define NFFT        1024
#define HOP         256
#define PADV        512
#define BATCH       16
#define F_BINS      513
#define N_FRAMES    1025
#define KF          512            // folded K

// GEMM tiling
#define BM 128
#define BN 128
#define BK 32
#define KITERS (KF / BK)           // 16
#define STAGES 4

#define AB_STRIDE 40               // halves per smem row (32 + 8 pad)
#define A_STAGE_BYTES (BM * AB_STRIDE * 2)   // 10240
#define B_STAGE_BYTES (BN * AB_STRIDE * 2)   // 10240
#define STAGE_BYTES   (A_STAGE_BYTES + B_STAGE_BYTES)
#define SMEM_TOTAL    (STAGES * STAGE_BYTES)  // 81920

// ---------------------------------------------------------------------------
// Device scratch
// ---------------------------------------------------------------------------
__device__ __half g_E[BATCH * N_FRAMES * KF];   // folded even frames  [b][t][j]
__device__ __half g_O[BATCH * N_FRAMES * KF];   // folded odd frames
__device__ __half g_BR[F_BINS * KF];            // folded real kernel  [f][j]
__device__ __half g_BI[F_BINS * KF];            // folded imag kernel

// ---------------------------------------------------------------------------
// PTX helpers (sm_100-safe)
// ---------------------------------------------------------------------------
__device__ __forceinline__ uint32_t smem_to_u32(const void* p) {
    uint32_t a;
    asm("{ .reg .u64 t; cvta.to.shared.u64 t, %1; cvt.u32.u64 %0, t; }"
        : "=r"(a) : "l"(p));
    return a;
}
__device__ __forceinline__ void cp_async16(uint32_t dst, const void* src) {
    asm volatile("cp.async.cg.shared.global [%0], [%1], 16;" :: "r"(dst), "l"(src));
}
#define CP_COMMIT() asm volatile("cp.async.commit_group;" ::: "memory")
#define CP_WAIT(N)  asm volatile("cp.async.wait_group %0;" :: "n"(N) : "memory")

__device__ __forceinline__ void ldmatrix_x4(uint32_t* r, uint32_t addr) {
    asm volatile("ldmatrix.sync.aligned.m8n8.x4.shared.b16 {%0,%1,%2,%3}, [%4];"
                 : "=r"(r[0]), "=r"(r[1]), "=r"(r[2]), "=r"(r[3]) : "r"(addr));
}
__device__ __forceinline__ void mma_16816(float* c, const uint32_t* a,
                                          uint32_t b0, uint32_t b1) {
    asm volatile(
        "mma.sync.aligned.m16n8k16.row.col.f32.f16.f16.f32 "
        "{%0,%1,%2,%3}, {%4,%5,%6,%7}, {%8,%9}, {%0,%1,%2,%3};"
        : "+f"(c[0]), "+f"(c[1]), "+f"(c[2]), "+f"(c[3])
        : "r"(a[0]), "r"(a[1]), "r"(a[2]), "r"(a[3]), "r"(b0), "r"(b1));
}

__device__ __forceinline__ int reflect_idx(int j) {   // padded coord -> signal idx
    int idx = j - PADV;
    idx = (idx < 0) ? -idx : idx;
    idx = (idx >= SIG_LEN) ? (2 * SIG_LEN - 2 - idx) : idx;
    return idx;
}

// ---------------------------------------------------------------------------
// Prologue 1: fold frames.  E[j]=f[j+1]+f[1023-j], O[j]=f[j+1]-f[1023-j]
// (j<511); E[511]=f[512], O[511]=0.   One warp per (b, t), t in [0,1024).
// ---------------------------------------------------------------------------
__global__ void fold_kernel(const float* __restrict__ sig) {
    int gw = (blockIdx.x * blockDim.x + threadIdx.x) >> 5;
    int lane = threadIdx.x & 31;
    if (gw >= BATCH * 1024) return;
    int b = gw >> 10, t = gw & 1023;
    const float* sg = sig + (size_t)b * SIG_LEN;
    const int p = t * HOP;
    __half* Ep = g_E + ((size_t)b * N_FRAMES + t) * KF;
    __half* Op = g_O + ((size_t)b * N_FRAMES + t) * KF;
    #pragma unroll
    for (int it = 0; it < 8; ++it) {
        int m = lane + it * 32;              // pair index, j0 = 2m
        int j0 = 2 * m;
        float a0 = sg[reflect_idx(p + j0 + 1)];
        float b0 = sg[reflect_idx(p + 1023 - j0)];
        float a1 = sg[reflect_idx(p + j0 + 2)];
        float b1 = sg[reflect_idx(p + 1022 - j0)];
        bool last = (m == 255);
        float e0 = a0 + b0, o0 = a0 - b0;
        float e1 = last ? a1 : a1 + b1;
        float o1 = last ? 0.f : a1 - b1;
        *reinterpret_cast<__half2*>(Ep + j0) =
            __floats2half2_rn(e0, e1);
        *reinterpret_cast<__half2*>(Op + j0) =
            __floats2half2_rn(o0, o1);
    }
}

// ---------------------------------------------------------------------------
// Prologue 2: folded kernel matrices.  BR[f][j]=ker[f][j+1] (j<511),
// BR[f][511]=ker[f][512];  BI[f][j]=ker[513+f][j+1] (j<511), BI[f][511]=0.
// ---------------------------------------------------------------------------
__global__ void ker_build_kernel(const float* __restrict__ ker) {
    int i = blockIdx.x * blockDim.x + threadIdx.x;
    if (i >= F_BINS * KF) return;
    int f = i / KF, j = i - f * KF;
    float r = (j < 511) ? ker[(size_t)f * NFFT + j + 1] : ker[(size_t)f * NFFT + 512];
    float im = (j < 511) ? ker[(size_t)(F_BINS + f) * NFFT + j + 1] : 0.f;
    g_BR[i] = __float2half(r);
    g_BI[i] = __float2half(im);
}

// ---------------------------------------------------------------------------
// Cleanup A: frame t=1024, all 1026 channels. Skinny 16x1026x1024 GEMM.
// Frames (fp16) in smem; ker rows broadcast across the 16 batch-threads.
// ---------------------------------------------------------------------------
__global__ void cleanup_last_frame(const float* __restrict__ sig,
                                   const float* __restrict__ ker,
                                   float* __restrict__ out) {
    __shared__ __half fr[BATCH][NFFT];        // 32 KB
    const int tid = threadIdx.x;
    for (int idx = tid; idx < BATCH * NFFT; idx += 256) {
        int b = idx >> 10, k = idx & 1023;
        fr[b][k] = __float2half(sig[(size_t)b * SIG_LEN +
                                    reflect_idx(1024 * HOP + k)]);
    }
    __syncthreads();
    const int bi = tid & 15, ci = tid >> 4;
    const int cp = blockIdx.x * 16 + ci;
    if (cp >= 1026) return;
    const int f = cp >> 1, ri = cp & 1;
    const float4* kr = reinterpret_cast<const float4*>(
        ker + (size_t)(ri * F_BINS + f) * NFFT);
    float acc = 0.f;
    #pragma unroll 4
    for (int q = 0; q < NFFT / 4; ++q) {
        float4 kv = kr[q];
        acc += __half2float(fr[bi][4 * q + 0]) * kv.x
             + __half2float(fr[bi][4 * q + 1]) * kv.y
             + __half2float(fr[bi][4 * q + 2]) * kv.z
             + __half2float(fr[bi][4 * q + 3]) * kv.w;
    }
    out[(((size_t)bi * F_BINS + f) * N_FRAMES + 1024) * 2 + ri] = acc;
}

// ---------------------------------------------------------------------------
// Cleanup B: bin f=512, all t. real = chunked correlation; imag == 0.
// One block per batch.  D[c][h] = dot(sig_chunk_h, w512[c*256..]) ;
// out[t] = D0[t]+D1[t+1]+D2[t+2]+D3[t+3].
// ---------------------------------------------------------------------------
__global__ void cleanup_last_bin(const float* __restrict__ sig,
                                 const float* __restrict__ ker,
                                 float* __restrict__ out) {
    __shared__ float w512[NFFT];
    __shared__ float D[4][1028];
    const int tid = threadIdx.x;
    const int b = blockIdx.x;
    const float* sg = sig + (size_t)b * SIG_LEN;
    for (int k = tid; k < NFFT; k += 256) w512[k] = ker[(size_t)512 * NFFT + k];
    __syncthreads();

    const int warp = tid >> 5, lane = tid & 31;
    for (int h = warp; h < 1028; h += 8) {
        float a0 = 0.f, a1 = 0.f, a2 = 0.f, a3 = 0.f;
        const int base = h * 256;
        #pragma unroll
        for (int q = 0; q < 8; ++q) {
            int j = lane + q * 32;
            float s = sg[reflect_idx(base + j)];
            a0 += s * w512[j];
            a1 += s * w512[256 + j];
            a2 += s * w512[512 + j];
            a3 += s * w512[768 + j];
        }
        #pragma unroll
        for (int o = 16; o; o >>= 1) {
            a0 += __shfl_xor_sync(0xffffffffu, a0, o);
            a1 += __shfl_xor_sync(0xffffffffu, a1, o);
            a2 += __shfl_xor_sync(0xffffffffu, a2, o);
            a3 += __shfl_xor_sync(0xffffffffu, a3, o);
        }
        if (lane == 0) { D[0][h] = a0; D[1][h] = a1; D[2][h] = a2; D[3][h] = a3; }
    }
    __syncthreads();
    for (int t = tid; t < N_FRAMES; t += 256) {
        float v = D[0][t] + D[1][t + 1] + D[2][t + 2] + D[3][t + 3];
        float* op = out + (((size_t)b * F_BINS + 512) * N_FRAMES + t) * 2;
        op[0] = v;
        op[1] = 0.f;            // imag(f=512) is identically ~0
    }
}

// ---------------------------------------------------------------------------
// Main GEMM: out_ri[t][f] = sum_j A[t][j] * B[f][j],  A=E/O, B=BR/BI, K=512
//   grid = (4 f-tiles, 8 t-tiles, 32 b*ri), block = 256 threads
//   warp grid 2(M) x 4(N), warp tile 64 x 32, mma.sync fp16, cp.async x4
// ---------------------------------------------------------------------------
__global__ void __launch_bounds__(256, 2) stft_gemm(float* __restrict__ out) {
    extern __shared__ __half smem[];
    const uint32_t sb = smem_to_u32(smem);
    const int tid = threadIdx.x;
    const int wid = tid >> 5;
    const int lane = tid & 31;
    const int n0 = blockIdx.x * BN;           // f-range start
    const int m0 = blockIdx.y * BM;           // t-range start
    const int b  = blockIdx.z >> 1;
    const int ri = blockIdx.z & 1;

    const __half* gA = (ri ? g_O : g_E) + (size_t)b * N_FRAMES * KF;
    const __half* gB = ri ? g_BI : g_BR;

    // cp.async assignments: 512 16B chunks each for A and B per stage
    const int r0 = tid >> 2,         c0 = tid & 3;
    const int r1 = (tid + 256) >> 2, c1 = (tid + 256) & 3;

    // ldmatrix lane decomposition (shared by A and B, both non-transposed)
    const int lm   = lane >> 3;
    const int l7   = lane & 7;
    const int row8 = (lm & 1) * 8 + l7;
    const int off8 = (lm >> 1) * 8;

    const int warp_m = wid & 1;
    const int warp_n = wid >> 1;

    float acc[4][4][4];
    #pragma unroll
    for (int i = 0; i < 4; ++i)
        #pragma unroll
        for (int j = 0; j < 4; ++j)
            #pragma unroll
            for (int v = 0; v < 4; ++v) acc[i][j][v] = 0.f;

    auto load_stage = [&](int s, int k0) {
        const uint32_t as = sb + s * STAGE_BYTES;
        const uint32_t bs = as + A_STAGE_BYTES;
        cp_async16(as + (r0 * AB_STRIDE + c0 * 8) * 2,
                   gA + (size_t)(m0 + r0) * KF + k0 + c0 * 8);
        cp_async16(as + (r1 * AB_STRIDE + c1 * 8) * 2,
                   gA + (size_t)(m0 + r1) * KF + k0 + c1 * 8);
        cp_async16(bs + (r0 * AB_STRIDE + c0 * 8) * 2,
                   gB + (size_t)(n0 + r0) * KF + k0 + c0 * 8);
        cp_async16(bs + (r1 * AB_STRIDE + c1 * 8) * 2,
                   gB + (size_t)(n0 + r1) * KF + k0 + c1 * 8);
    };

    #pragma unroll
    for (int s = 0; s < STAGES - 1; ++s) {
        load_stage(s, s * BK);
        CP_COMMIT();
    }

    for (int i = 0; i < KITERS; ++i) {
        CP_WAIT(STAGES - 2);
        __syncthreads();

        const int s = i & (STAGES - 1);
        const uint32_t as = sb + s * STAGE_BYTES;
        const uint32_t bs = as + A_STAGE_BYTES;

        #pragma unroll
        for (int ks = 0; ks < BK; ks += 16) {
            uint32_t A[4][4];
            #pragma unroll
            for (int mf = 0; mf < 4; ++mf) {
                const int row = warp_m * 64 + mf * 16 + row8;
                ldmatrix_x4(A[mf], as + (row * AB_STRIDE + ks + off8) * 2);
            }
            uint32_t Bv[4][2];
            #pragma unroll
            for (int p = 0; p < 2; ++p) {
                const int nrow = warp_n * 32 + p * 16 + row8;
                uint32_t r[4];
                ldmatrix_x4(r, bs + (nrow * AB_STRIDE + ks + off8) * 2);
                Bv[2 * p][0]     = r[0]; Bv[2 * p][1]     = r[2];
                Bv[2 * p + 1][0] = r[1]; Bv[2 * p + 1][1] = r[3];
            }
            #pragma unroll
            for (int mf = 0; mf < 4; ++mf)
                #pragma unroll
                for (int nf = 0; nf < 4; ++nf)
                    mma_16816(acc[mf][nf], A[mf], Bv[nf][0], Bv[nf][1]);
        }

        if (i + STAGES - 1 < KITERS)
            load_stage((i + STAGES - 1) & (STAGES - 1), (i + STAGES - 1) * BK);
        CP_COMMIT();
    }

    // epilogue: out[b][f][t][ri]
    const int t_base = m0 + warp_m * 64 + (lane >> 2);
    const int f_base = n0 + warp_n * 32 + 2 * (lane & 3);
    float* ob = out + ((size_t)b * F_BINS) * (size_t)N_FRAMES * 2 + ri;

    #pragma unroll
    for (int mf = 0; mf < 4; ++mf) {
        const int t0 = t_base + mf * 16;
        #pragma unroll
        for (int nf = 0; nf < 4; ++nf) {
            const int f0 = f_base + nf * 8;
            float* p0 = ob + ((size_t)f0 * N_FRAMES + t0) * 2;
            float* p1 = ob + ((size_t)(f0 + 1) * N_FRAMES + t0) * 2;
            p0[0]  = acc[mf][nf][0];
            p1[0]  = acc[mf][nf][1];
            p0[16] = acc[mf][nf][2];   // t0+8, stride 2 floats
            p1[16] = acc[mf][nf][3];
        }
    }
}

// ---------------------------------------------------------------------------
// Host launcher
// ---------------------------------------------------------------------------
extern "C" void kernel_launch(void* const* d_in, const int* in_sizes, int n_in,
                              void* d_out, int out_size) {
    (void)in_sizes; (void)n_in; (void)out_size;
    const float* signal = (const float*)d_in[0];   // [16, 262144] fp32
    const float* kernel = (const float*)d_in[1];   // [1026, 1024] fp32
    float* out = (float*)d_out;                    // [16, 513, 1025, 2] fp32

    // Prologue: fold frames + build folded kernel matrices
    fold_kernel<<<BATCH * 1024 / 8, 256>>>(signal);         // 8 warps/block
    ker_build_kernel<<<(F_BINS * KF + 255) / 256, 256>>>(kernel);

    // Main folded GEMM (t<1024, f<512, both ri)
    static bool attr_set = false;
    if (!attr_set) {
        cudaFuncSetAttribute(stft_gemm,
                             cudaFuncAttributeMaxDynamicSharedMemorySize,
                             SMEM_TOTAL);
        attr_set = true;
    }
    stft_gemm<<<dim3(4, 8, 2 * BATCH), 256, SMEM_TOTAL>>>(out);

    // Cleanups (independent of prologue; exact-ish paths from raw inputs)
    cleanup_last_frame<<<(1026 + 15) / 16, 256>>>(signal, kernel, out);
    cleanup_last_bin<<<BATCH, 256>>>(signal, kernel, out);
}

// round 4
// speedup vs baseline: 2.7117x; 2.7117x over previous
#include <cuda_runtime.h>
#include <cuda_fp16.h>
#include <cstdint>

// ---------------------------------------------------------------------------
// Problem constants
// ---------------------------------------------------------------------------
#define SIG_LEN     262144
#define NFFT        1024
#define HOP         256
#define PADV        512
#define BATCH       16
#define F_BINS      513
#define N_FRAMES    1025
#define KF          512            // folded K

// GEMM tiling
#define BM 128
#define BN 128
#define BK 32
#define KITERS (KF / BK)           // 16
#define STAGES 4

#define AB_STRIDE 40               // halves per smem row (32 + 8 pad)
#define A_STAGE_BYTES (BM * AB_STRIDE * 2)   // 10240
#define B_STAGE_BYTES (BN * AB_STRIDE * 2)   // 10240
#define STAGE_BYTES   (A_STAGE_BYTES + B_STAGE_BYTES)
#define SMEM_TOTAL    (STAGES * STAGE_BYTES)  // 81920

// fold kernel staging
#define FOLD_FRAMES 16
#define FOLD_SPAN   (FOLD_FRAMES * HOP + NFFT)   // 5120 floats

// ---------------------------------------------------------------------------
// Device scratch
// ---------------------------------------------------------------------------
__device__ __half g_E[BATCH * N_FRAMES * KF];   // folded even frames  [b][t][j]
__device__ __half g_O[BATCH * N_FRAMES * KF];   // folded odd frames
__device__ __half g_BR[F_BINS * KF];            // folded real kernel  [f][j]
__device__ __half g_BI[F_BINS * KF];            // folded imag kernel

// ---------------------------------------------------------------------------
// PTX helpers (sm_100-safe)
// ---------------------------------------------------------------------------
__device__ __forceinline__ uint32_t smem_to_u32(const void* p) {
    uint32_t a;
    asm("{ .reg .u64 t; cvta.to.shared.u64 t, %1; cvt.u32.u64 %0, t; }"
        : "=r"(a) : "l"(p));
    return a;
}
__device__ __forceinline__ void cp_async16(uint32_t dst, const void* src) {
    asm volatile("cp.async.cg.shared.global [%0], [%1], 16;" :: "r"(dst), "l"(src));
}
#define CP_COMMIT() asm volatile("cp.async.commit_group;" ::: "memory")
#define CP_WAIT(N)  asm volatile("cp.async.wait_group %0;" :: "n"(N) : "memory")

__device__ __forceinline__ void ldmatrix_x4(uint32_t* r, uint32_t addr) {
    asm volatile("ldmatrix.sync.aligned.m8n8.x4.shared.b16 {%0,%1,%2,%3}, [%4];"
                 : "=r"(r[0]), "=r"(r[1]), "=r"(r[2]), "=r"(r[3]) : "r"(addr));
}
__device__ __forceinline__ void mma_16816(float* c, const uint32_t* a,
                                          uint32_t b0, uint32_t b1) {
    asm volatile(
        "mma.sync.aligned.m16n8k16.row.col.f32.f16.f16.f32 "
        "{%0,%1,%2,%3}, {%4,%5,%6,%7}, {%8,%9}, {%0,%1,%2,%3};"
        : "+f"(c[0]), "+f"(c[1]), "+f"(c[2]), "+f"(c[3])
        : "r"(a[0]), "r"(a[1]), "r"(a[2]), "r"(a[3]), "r"(b0), "r"(b1));
}

__device__ __forceinline__ int reflect_idx(int j) {   // padded coord -> signal idx
    int idx = j - PADV;
    idx = (idx < 0) ? -idx : idx;
    idx = (idx >= SIG_LEN) ? (2 * SIG_LEN - 2 - idx) : idx;
    return idx;
}

// ---------------------------------------------------------------------------
// Prologue 1: fold frames via smem staging.
//   E[j]=f[j+1]+f[1023-j], O[j]=f[j+1]-f[1023-j]  (j<511);
//   E[511]=f[512], O[511]=0.
//   Block = 16 consecutive frames of one batch; signal window staged in smem.
//   grid = (65, 16): chunk 64 covers frames 1024 (only frame 1024 used).
// ---------------------------------------------------------------------------
__global__ void __launch_bounds__(256) fold_kernel(const float* __restrict__ sig) {
    __shared__ float s[FOLD_SPAN];
    const int tid = threadIdx.x;
    const int b = blockIdx.y;
    const int t0 = blockIdx.x * FOLD_FRAMES;
    const int base = t0 * HOP;
    const float* sg = sig + (size_t)b * SIG_LEN;

    #pragma unroll 5
    for (int i = tid; i < FOLD_SPAN; i += 256)
        s[i] = sg[reflect_idx(base + i)];
    __syncthreads();

    const int warp = tid >> 5, lane = tid & 31;
    const int nfr = (t0 == 1024) ? 1 : FOLD_FRAMES;   // last chunk: 1 frame
    for (int lt = warp; lt < nfr; lt += 8) {
        const int t = t0 + lt;
        const float* w = s + lt * HOP;
        __half2* Ep = reinterpret_cast<__half2*>(g_E + ((size_t)b * N_FRAMES + t) * KF);
        __half2* Op = reinterpret_cast<__half2*>(g_O + ((size_t)b * N_FRAMES + t) * KF);
        #pragma unroll
        for (int it = 0; it < 8; ++it) {
            int m = lane + it * 32;         // half2 index; j0 = 2m
            int j0 = 2 * m;
            float a0 = w[j0 + 1];
            float b0 = w[1023 - j0];
            float a1 = w[j0 + 2];
            float b1 = w[1022 - j0];
            bool last = (m == 255);
            float e0 = a0 + b0, o0 = a0 - b0;
            float e1 = last ? a1 : a1 + b1;
            float o1 = last ? 0.f : a1 - b1;
            Ep[m] = __floats2half2_rn(e0, e1);
            Op[m] = __floats2half2_rn(o0, o1);
        }
    }
}

// ---------------------------------------------------------------------------
// Prologue 2: folded kernel matrices.  BR[f][j]=ker[f][j+1] (j<511),
// BR[f][511]=ker[f][512];  BI[f][j]=ker[513+f][j+1] (j<511), BI[f][511]=0.
// ---------------------------------------------------------------------------
__global__ void ker_build_kernel(const float* __restrict__ ker) {
    int i = blockIdx.x * blockDim.x + threadIdx.x;
    if (i >= F_BINS * KF) return;
    int f = i / KF, j = i - f * KF;
    float r = (j < 511) ? ker[(size_t)f * NFFT + j + 1] : ker[(size_t)f * NFFT + 512];
    float im = (j < 511) ? ker[(size_t)(F_BINS + f) * NFFT + j + 1] : 0.f;
    g_BR[i] = __float2half(r);
    g_BI[i] = __float2half(im);
}

// ---------------------------------------------------------------------------
// Edge A: frame t=1024, all f, both ri — from folded data.
//   One warp per (b, f).  grid = 16*513/8 blocks of 8 warps.
// ---------------------------------------------------------------------------
__global__ void __launch_bounds__(256) edge_last_frame(float* __restrict__ out) {
    const int gw = (blockIdx.x * blockDim.x + threadIdx.x) >> 5;
    const int lane = threadIdx.x & 31;
    if (gw >= BATCH * F_BINS) return;
    const int b = gw / F_BINS, f = gw - b * F_BINS;
    const __half2* E = reinterpret_cast<const __half2*>(
        g_E + ((size_t)b * N_FRAMES + 1024) * KF);
    const __half2* O = reinterpret_cast<const __half2*>(
        g_O + ((size_t)b * N_FRAMES + 1024) * KF);
    const __half2* R = reinterpret_cast<const __half2*>(g_BR + (size_t)f * KF);
    const __half2* I = reinterpret_cast<const __half2*>(g_BI + (size_t)f * KF);
    float ar = 0.f, ai = 0.f;
    #pragma unroll
    for (int q = 0; q < 8; ++q) {
        int m = lane + q * 32;
        float2 e = __half22float2(E[m]), r = __half22float2(R[m]);
        float2 o = __half22float2(O[m]), i2 = __half22float2(I[m]);
        ar += e.x * r.x + e.y * r.y;
        ai += o.x * i2.x + o.y * i2.y;
    }
    #pragma unroll
    for (int off = 16; off; off >>= 1) {
        ar += __shfl_xor_sync(0xffffffffu, ar, off);
        ai += __shfl_xor_sync(0xffffffffu, ai, off);
    }
    if (lane == 0) {
        float* op = out + (((size_t)b * F_BINS + f) * N_FRAMES + 1024) * 2;
        op[0] = ar;
        op[1] = ai;
    }
}

// ---------------------------------------------------------------------------
// Edge B: bin f=512, t<1024 — real = E[b][t]·BR[512], imag = 0.
//   One warp per (b, t).  grid = 16*1024/8.
// ---------------------------------------------------------------------------
__global__ void __launch_bounds__(256) edge_last_bin(float* __restrict__ out) {
    const int gw = (blockIdx.x * blockDim.x + threadIdx.x) >> 5;
    const int lane = threadIdx.x & 31;
    if (gw >= BATCH * 1024) return;
    const int b = gw >> 10, t = gw & 1023;
    const __half2* E = reinterpret_cast<const __half2*>(
        g_E + ((size_t)b * N_FRAMES + t) * KF);
    const __half2* R = reinterpret_cast<const __half2*>(g_BR + (size_t)512 * KF);
    float ar = 0.f;
    #pragma unroll
    for (int q = 0; q < 8; ++q) {
        int m = lane + q * 32;
        float2 e = __half22float2(E[m]), r = __half22float2(R[m]);
        ar += e.x * r.x + e.y * r.y;
    }
    #pragma unroll
    for (int off = 16; off; off >>= 1)
        ar += __shfl_xor_sync(0xffffffffu, ar, off);
    if (lane == 0) {
        float* op = out + (((size_t)b * F_BINS + 512) * N_FRAMES + t) * 2;
        op[0] = ar;
        op[1] = 0.f;
    }
}

// ---------------------------------------------------------------------------
// Main GEMM: out_ri[t][f] = sum_j A[t][j] * B[f][j],  A=E/O, B=BR/BI, K=512
//   grid = (4 f-tiles, 8 t-tiles, 32 b*ri), block = 256 threads
//   warp grid 2(M) x 4(N), warp tile 64 x 32, mma.sync fp16, cp.async x4
// ---------------------------------------------------------------------------
__global__ void __launch_bounds__(256, 2) stft_gemm(float* __restrict__ out) {
    extern __shared__ __half smem[];
    const uint32_t sb = smem_to_u32(smem);
    const int tid = threadIdx.x;
    const int wid = tid >> 5;
    const int lane = tid & 31;
    const int n0 = blockIdx.x * BN;           // f-range start
    const int m0 = blockIdx.y * BM;           // t-range start
    const int b  = blockIdx.z >> 1;
    const int ri = blockIdx.z & 1;

    const __half* gA = (ri ? g_O : g_E) + (size_t)b * N_FRAMES * KF;
    const __half* gB = ri ? g_BI : g_BR;

    const int r0 = tid >> 2,         c0 = tid & 3;
    const int r1 = (tid + 256) >> 2, c1 = (tid + 256) & 3;

    const int lm   = lane >> 3;
    const int l7   = lane & 7;
    const int row8 = (lm & 1) * 8 + l7;
    const int off8 = (lm >> 1) * 8;

    const int warp_m = wid & 1;
    const int warp_n = wid >> 1;

    float acc[4][4][4];
    #pragma unroll
    for (int i = 0; i < 4; ++i)
        #pragma unroll
        for (int j = 0; j < 4; ++j)
            #pragma unroll
            for (int v = 0; v < 4; ++v) acc[i][j][v] = 0.f;

    auto load_stage = [&](int s, int k0) {
        const uint32_t as = sb + s * STAGE_BYTES;
        const uint32_t bs = as + A_STAGE_BYTES;
        cp_async16(as + (r0 * AB_STRIDE + c0 * 8) * 2,
                   gA + (size_t)(m0 + r0) * KF + k0 + c0 * 8);
        cp_async16(as + (r1 * AB_STRIDE + c1 * 8) * 2,
                   gA + (size_t)(m0 + r1) * KF + k0 + c1 * 8);
        cp_async16(bs + (r0 * AB_STRIDE + c0 * 8) * 2,
                   gB + (size_t)(n0 + r0) * KF + k0 + c0 * 8);
        cp_async16(bs + (r1 * AB_STRIDE + c1 * 8) * 2,
                   gB + (size_t)(n0 + r1) * KF + k0 + c1 * 8);
    };

    #pragma unroll
    for (int s = 0; s < STAGES - 1; ++s) {
        load_stage(s, s * BK);
        CP_COMMIT();
    }

    for (int i = 0; i < KITERS; ++i) {
        CP_WAIT(STAGES - 2);
        __syncthreads();

        const int s = i & (STAGES - 1);
        const uint32_t as = sb + s * STAGE_BYTES;
        const uint32_t bs = as + A_STAGE_BYTES;

        #pragma unroll
        for (int ks = 0; ks < BK; ks += 16) {
            uint32_t A[4][4];
            #pragma unroll
            for (int mf = 0; mf < 4; ++mf) {
                const int row = warp_m * 64 + mf * 16 + row8;
                ldmatrix_x4(A[mf], as + (row * AB_STRIDE + ks + off8) * 2);
            }
            uint32_t Bv[4][2];
            #pragma unroll
            for (int p = 0; p < 2; ++p) {
                const int nrow = warp_n * 32 + p * 16 + row8;
                uint32_t r[4];
                ldmatrix_x4(r, bs + (nrow * AB_STRIDE + ks + off8) * 2);
                Bv[2 * p][0]     = r[0]; Bv[2 * p][1]     = r[2];
                Bv[2 * p + 1][0] = r[1]; Bv[2 * p + 1][1] = r[3];
            }
            #pragma unroll
            for (int mf = 0; mf < 4; ++mf)
                #pragma unroll
                for (int nf = 0; nf < 4; ++nf)
                    mma_16816(acc[mf][nf], A[mf], Bv[nf][0], Bv[nf][1]);
        }

        if (i + STAGES - 1 < KITERS)
            load_stage((i + STAGES - 1) & (STAGES - 1), (i + STAGES - 1) * BK);
        CP_COMMIT();
    }

    // epilogue: out[b][f][t][ri]
    const int t_base = m0 + warp_m * 64 + (lane >> 2);
    const int f_base = n0 + warp_n * 32 + 2 * (lane & 3);
    float* ob = out + ((size_t)b * F_BINS) * (size_t)N_FRAMES * 2 + ri;

    #pragma unroll
    for (int mf = 0; mf < 4; ++mf) {
        const int t0 = t_base + mf * 16;
        #pragma unroll
        for (int nf = 0; nf < 4; ++nf) {
            const int f0 = f_base + nf * 8;
            float* p0 = ob + ((size_t)f0 * N_FRAMES + t0) * 2;
            float* p1 = ob + ((size_t)(f0 + 1) * N_FRAMES + t0) * 2;
            p0[0]  = acc[mf][nf][0];
            p1[0]  = acc[mf][nf][1];
            p0[16] = acc[mf][nf][2];   // t0+8, stride 2 floats
            p1[16] = acc[mf][nf][3];
        }
    }
}

// ---------------------------------------------------------------------------
// Host launcher
// ---------------------------------------------------------------------------
extern "C" void kernel_launch(void* const* d_in, const int* in_sizes, int n_in,
                              void* d_out, int out_size) {
    (void)in_sizes; (void)n_in; (void)out_size;
    const float* signal = (const float*)d_in[0];   // [16, 262144] fp32
    const float* kernel = (const float*)d_in[1];   // [1026, 1024] fp32
    float* out = (float*)d_out;                    // [16, 513, 1025, 2] fp32

    // Prologue: fold frames (65 chunks x 16 batches) + folded kernel matrices
    fold_kernel<<<dim3(65, BATCH), 256>>>(signal);
    ker_build_kernel<<<(F_BINS * KF + 255) / 256, 256>>>(kernel);

    // Main folded GEMM (t<1024, f<512, both ri)
    static bool attr_set = false;
    if (!attr_set) {
        cudaFuncSetAttribute(stft_gemm,
                             cudaFuncAttributeMaxDynamicSharedMemorySize,
                             SMEM_TOTAL);
        attr_set = true;
    }
    stft_gemm<<<dim3(4, 8, 2 * BATCH), 256, SMEM_TOTAL>>>(out);

    // Edges from folded data (t=1024 all f; f=512 t<1024)
    edge_last_frame<<<(BATCH * F_BINS + 7) / 8, 256>>>(out);
    edge_last_bin<<<BATCH * 1024 / 8, 256>>>(out);
}

// round 5
// speedup vs baseline: 3.3443x; 1.2333x over previous
#include <cuda_runtime.h>
#include <cuda_fp16.h>
#include <cstdint>

// ---------------------------------------------------------------------------
// Problem constants
// ---------------------------------------------------------------------------
#define SIG_LEN     262144
#define NFFT        1024
#define HOP         256
#define PADV        512
#define BATCH       16
#define F_BINS      513
#define N_FRAMES    1025
#define KF2         256            // twice-folded K

// GEMM tiling
#define BM 128
#define BN 128
#define BK 32
#define KITERS (KF2 / BK)          // 8
#define STAGES 4

#define AB_STRIDE 40               // halves per smem row (32 + 8 pad)
#define A_STAGE_BYTES (BM * AB_STRIDE * 2)   // 10240
#define B_STAGE_BYTES (BN * AB_STRIDE * 2)   // 10240
#define STAGE_BYTES   (A_STAGE_BYTES + B_STAGE_BYTES)
#define SMEM_TOTAL    (STAGES * STAGE_BYTES)  // 81920

// fold kernel staging
#define FOLD_FRAMES 16
#define FOLD_SPAN   (FOLD_FRAMES * HOP + NFFT)   // 5120 floats

// ---------------------------------------------------------------------------
// Device scratch.  Classes: 0=RE (real,even f), 1=RO (real,odd), 2=IE, 3=IO
// ---------------------------------------------------------------------------
__device__ __half g_A[4][BATCH * N_FRAMES * KF2];  // frames per class [b][t][s]
__device__ __half g_K[4][KF2 * KF2];               // kernels per class [g][s]
__device__ float  g_E512[BATCH * N_FRAMES];        // y[512] per (b,t)

// ---------------------------------------------------------------------------
// PTX helpers (sm_100-safe)
// ---------------------------------------------------------------------------
__device__ __forceinline__ uint32_t smem_to_u32(const void* p) {
    uint32_t a;
    asm("{ .reg .u64 t; cvta.to.shared.u64 t, %1; cvt.u32.u64 %0, t; }"
        : "=r"(a) : "l"(p));
    return a;
}
__device__ __forceinline__ void cp_async16(uint32_t dst, const void* src) {
    asm volatile("cp.async.cg.shared.global [%0], [%1], 16;" :: "r"(dst), "l"(src));
}
#define CP_COMMIT() asm volatile("cp.async.commit_group;" ::: "memory")
#define CP_WAIT(N)  asm volatile("cp.async.wait_group %0;" :: "n"(N) : "memory")

__device__ __forceinline__ void ldmatrix_x4(uint32_t* r, uint32_t addr) {
    asm volatile("ldmatrix.sync.aligned.m8n8.x4.shared.b16 {%0,%1,%2,%3}, [%4];"
                 : "=r"(r[0]), "=r"(r[1]), "=r"(r[2]), "=r"(r[3]) : "r"(addr));
}
__device__ __forceinline__ void mma_16816(float* c, const uint32_t* a,
                                          uint32_t b0, uint32_t b1) {
    asm volatile(
        "mma.sync.aligned.m16n8k16.row.col.f32.f16.f16.f32 "
        "{%0,%1,%2,%3}, {%4,%5,%6,%7}, {%8,%9}, {%0,%1,%2,%3};"
        : "+f"(c[0]), "+f"(c[1]), "+f"(c[2]), "+f"(c[3])
        : "r"(a[0]), "r"(a[1]), "r"(a[2]), "r"(a[3]), "r"(b0), "r"(b1));
}

__device__ __forceinline__ int reflect_idx(int j) {   // padded coord -> signal idx
    int idx = j - PADV;
    idx = (idx < 0) ? -idx : idx;
    idx = (idx >= SIG_LEN) ? (2 * SIG_LEN - 2 - idx) : idx;
    return idx;
}

// ---------------------------------------------------------------------------
// Fold: window frames (y[k]=x[k]w[k]) and apply two DFT folds.
//   E[j]=y[j]+y[1024-j], O[j]=y[j]-y[1024-j]  (j=1..511), E[512]=y[512]
//   For slot s (j=s+1, s=0..254):
//     RE[s]=E[j]+E[512-j]  RO[s]=E[j]-E[512-j]
//     IE[s]=O[j]-O[512-j]  IO[s]=O[j]+O[512-j]
//   slot 255: RE=E[256], RO=E[512], IE=0, IO=O[256]
//   Also store g_E512 = y[512] (fp32) for the even-f real epilogue term.
//   Window folds: w[1024-j]=w[j], w[512±j]=1-w[j]  (Hann).
// ---------------------------------------------------------------------------
__global__ void __launch_bounds__(256) fold_kernel(const float* __restrict__ sig) {
    __shared__ float s[FOLD_SPAN];
    __shared__ float wv[257];
    const int tid = threadIdx.x;
    const int b = blockIdx.y;
    const int t0 = blockIdx.x * FOLD_FRAMES;
    const int base = t0 * HOP;
    const float* sg = sig + (size_t)b * SIG_LEN;

    #pragma unroll 5
    for (int i = tid; i < FOLD_SPAN; i += 256)
        s[i] = sg[reflect_idx(base + i)];
    for (int i = tid; i <= 256; i += 256)
        wv[i] = 0.5f - 0.5f * cospif((float)i / 512.0f);
    __syncthreads();

    const int warp = tid >> 5, lane = tid & 31;
    const int nfr = (t0 == 1024) ? 1 : FOLD_FRAMES;
    for (int lt = warp; lt < nfr; lt += 8) {
        const int t = t0 + lt;
        const float* sf = s + lt * HOP;
        const size_t ro = ((size_t)b * N_FRAMES + t) * KF2;
        __half2* RE = reinterpret_cast<__half2*>(g_A[0] + ro);
        __half2* RO = reinterpret_cast<__half2*>(g_A[1] + ro);
        __half2* IE = reinterpret_cast<__half2*>(g_A[2] + ro);
        __half2* IO = reinterpret_cast<__half2*>(g_A[3] + ro);
        if (lane == 0)
            g_E512[b * N_FRAMES + t] = sf[512];   // w[512] = 1
        #pragma unroll
        for (int qq = 0; qq < 4; ++qq) {
            const int m = lane + qq * 32;          // half2 index: slots 2m, 2m+1
            float re[2], rr[2], ie[2], io[2];
            #pragma unroll
            for (int u = 0; u < 2; ++u) {
                const int ss = 2 * m + u;
                const int j = ss + 1;              // 1..256
                const float wj = wv[j];
                const float wc = 1.0f - wj;
                const float yj  = sf[j]        * wj;
                const float ymj = sf[1024 - j] * wj;
                const float ya  = sf[512 - j]  * wc;
                const float yb  = sf[512 + j]  * wc;
                const float uu = yj + ymj, vv = yj - ymj;
                const float pp = ya + yb,  q2 = ya - yb;
                re[u] = uu + pp;  rr[u] = uu - pp;
                ie[u] = vv - q2;  io[u] = vv + q2;
                if (ss == 255) {                   // j=256 self-pair + E512 slot
                    re[u] = uu;                    // E[256]
                    rr[u] = sf[512];               // E[512] = y[512]
                    io[u] = vv;                    // O[256]
                    ie[u] = 0.f;
                }
            }
            RE[m] = __floats2half2_rn(re[0], re[1]);
            RO[m] = __floats2half2_rn(rr[0], rr[1]);
            IE[m] = __floats2half2_rn(ie[0], ie[1]);
            IO[m] = __floats2half2_rn(io[0], io[1]);
        }
    }
}

// ---------------------------------------------------------------------------
// Kernel matrices (analytic, g=0..255, slot s=0..255, j=s+1):
//   RE[g][s] = cos(pi*g*j/256)          (j=256 -> (-1)^g, pairs with E[256])
//   RO[g][s] = cos(pi*(2g+1)*j/512) for s<255 ; slot255 = -1 (E[512] coeff)
//   IE[g][s] = -sin(pi*g*j/256)
//   IO[g][s] = -sin(pi*(2g+1)*j/512)    (j=256 -> -(-1)^g, pairs with O[256])
// ---------------------------------------------------------------------------
__global__ void ker_build_kernel() {
    const int i = blockIdx.x * blockDim.x + threadIdx.x;
    if (i >= KF2 * KF2) return;
    const int g = i >> 8, ss = i & 255;
    const float j = (float)(ss + 1);
    const float ge = (float)g * j * (1.0f / 256.0f);
    const float go = (float)(2 * g + 1) * j * (1.0f / 512.0f);
    g_K[0][i] = __float2half(cospif(ge));
    g_K[1][i] = __float2half((ss < 255) ? cospif(go) : -1.0f);
    g_K[2][i] = __float2half(-sinpif(ge));
    g_K[3][i] = __float2half(-sinpif(go));
}

// ---------------------------------------------------------------------------
// Edge A: frame t=1024, f=0..512, both ri.  One warp per (b,f).
// ---------------------------------------------------------------------------
__global__ void __launch_bounds__(256) edge_last_frame(float* __restrict__ out) {
    const int gw = (blockIdx.x * blockDim.x + threadIdx.x) >> 5;
    const int lane = threadIdx.x & 31;
    if (gw >= BATCH * F_BINS) return;
    const int b = gw / F_BINS, f = gw - b * F_BINS;
    const size_t ro = ((size_t)b * N_FRAMES + 1024) * KF2;
    float ar = 0.f, ai = 0.f;
    if (f == 512) {
        const __half2* A = reinterpret_cast<const __half2*>(g_A[0] + ro);
        #pragma unroll
        for (int q = 0; q < 4; ++q) {
            float2 a = __half22float2(A[lane + q * 32]);
            ar += a.y - a.x;                 // sign (-1)^(s+1)
        }
    } else {
        const int p = f & 1, g = f >> 1;
        const __half2* Ar = reinterpret_cast<const __half2*>(g_A[p] + ro);
        const __half2* Kr = reinterpret_cast<const __half2*>(g_K[p] + (size_t)g * KF2);
        const __half2* Ai = reinterpret_cast<const __half2*>(g_A[2 + p] + ro);
        const __half2* Ki = reinterpret_cast<const __half2*>(g_K[2 + p] + (size_t)g * KF2);
        #pragma unroll
        for (int q = 0; q < 4; ++q) {
            const int m = lane + q * 32;
            float2 a = __half22float2(Ar[m]), k = __half22float2(Kr[m]);
            float2 c = __half22float2(Ai[m]), d = __half22float2(Ki[m]);
            ar += a.x * k.x + a.y * k.y;
            ai += c.x * d.x + c.y * d.y;
        }
    }
    #pragma unroll
    for (int off = 16; off; off >>= 1) {
        ar += __shfl_xor_sync(0xffffffffu, ar, off);
        ai += __shfl_xor_sync(0xffffffffu, ai, off);
    }
    if (lane == 0) {
        if ((f & 1) == 0) ar += g_E512[b * N_FRAMES + 1024];  // even-f real term
        if (f == 512) ai = 0.f;
        float* op = out + (((size_t)b * F_BINS + f) * N_FRAMES + 1024) * 2;
        op[0] = ar;
        op[1] = ai;
    }
}

// ---------------------------------------------------------------------------
// Edge B: bin f=512, t<1024.  real = sum_s RE[s]*(-1)^(s+1) + E512; imag = 0.
// ---------------------------------------------------------------------------
__global__ void __launch_bounds__(256) edge_last_bin(float* __restrict__ out) {
    const int gw = (blockIdx.x * blockDim.x + threadIdx.x) >> 5;
    const int lane = threadIdx.x & 31;
    if (gw >= BATCH * 1024) return;
    const int b = gw >> 10, t = gw & 1023;
    const __half2* A = reinterpret_cast<const __half2*>(
        g_A[0] + ((size_t)b * N_FRAMES + t) * KF2);
    float ar = 0.f;
    #pragma unroll
    for (int q = 0; q < 4; ++q) {
        float2 a = __half22float2(A[lane + q * 32]);
        ar += a.y - a.x;
    }
    #pragma unroll
    for (int off = 16; off; off >>= 1)
        ar += __shfl_xor_sync(0xffffffffu, ar, off);
    if (lane == 0) {
        float* op = out + (((size_t)b * F_BINS + 512) * N_FRAMES + t) * 2;
        op[0] = ar + g_E512[b * N_FRAMES + t];
        op[1] = 0.f;
    }
}

// ---------------------------------------------------------------------------
// Main GEMM: per class c, out_c[t][g] = sum_s A_c[t][s] * K_c[g][s], K=256.
//   grid = (2 g-tiles, 8 t-tiles, 64 = 16b x 4cls), block = 256 threads
//   warp grid 2(M) x 4(N), warp tile 64 x 32, mma.sync fp16, cp.async x4
// ---------------------------------------------------------------------------
__global__ void __launch_bounds__(256, 2) stft_gemm(float* __restrict__ out) {
    extern __shared__ __half smem[];
    const uint32_t sb = smem_to_u32(smem);
    const int tid = threadIdx.x;
    const int wid = tid >> 5;
    const int lane = tid & 31;
    const int n0 = blockIdx.x * BN;           // g-range start
    const int m0 = blockIdx.y * BM;           // t-range start
    const int b   = blockIdx.z & 15;
    const int cls = blockIdx.z >> 4;

    const __half* gA = g_A[cls] + (size_t)b * N_FRAMES * KF2;
    const __half* gB = g_K[cls];

    const int r0 = tid >> 2,         c0 = tid & 3;
    const int r1 = (tid + 256) >> 2, c1 = (tid + 256) & 3;

    const int lm   = lane >> 3;
    const int l7   = lane & 7;
    const int row8 = (lm & 1) * 8 + l7;
    const int off8 = (lm >> 1) * 8;

    const int warp_m = wid & 1;
    const int warp_n = wid >> 1;

    float acc[4][4][4];
    #pragma unroll
    for (int i = 0; i < 4; ++i)
        #pragma unroll
        for (int j = 0; j < 4; ++j)
            #pragma unroll
            for (int v = 0; v < 4; ++v) acc[i][j][v] = 0.f;

    auto load_stage = [&](int s, int k0) {
        const uint32_t as = sb + s * STAGE_BYTES;
        const uint32_t bs = as + A_STAGE_BYTES;
        cp_async16(as + (r0 * AB_STRIDE + c0 * 8) * 2,
                   gA + (size_t)(m0 + r0) * KF2 + k0 + c0 * 8);
        cp_async16(as + (r1 * AB_STRIDE + c1 * 8) * 2,
                   gA + (size_t)(m0 + r1) * KF2 + k0 + c1 * 8);
        cp_async16(bs + (r0 * AB_STRIDE + c0 * 8) * 2,
                   gB + (size_t)(n0 + r0) * KF2 + k0 + c0 * 8);
        cp_async16(bs + (r1 * AB_STRIDE + c1 * 8) * 2,
                   gB + (size_t)(n0 + r1) * KF2 + k0 + c1 * 8);
    };

    #pragma unroll
    for (int s = 0; s < STAGES - 1; ++s) {
        load_stage(s, s * BK);
        CP_COMMIT();
    }

    for (int i = 0; i < KITERS; ++i) {
        CP_WAIT(STAGES - 2);
        __syncthreads();

        const int s = i & (STAGES - 1);
        const uint32_t as = sb + s * STAGE_BYTES;
        const uint32_t bs = as + A_STAGE_BYTES;

        #pragma unroll
        for (int ks = 0; ks < BK; ks += 16) {
            uint32_t A[4][4];
            #pragma unroll
            for (int mf = 0; mf < 4; ++mf) {
                const int row = warp_m * 64 + mf * 16 + row8;
                ldmatrix_x4(A[mf], as + (row * AB_STRIDE + ks + off8) * 2);
            }
            uint32_t Bv[4][2];
            #pragma unroll
            for (int p = 0; p < 2; ++p) {
                const int nrow = warp_n * 32 + p * 16 + row8;
                uint32_t r[4];
                ldmatrix_x4(r, bs + (nrow * AB_STRIDE + ks + off8) * 2);
                Bv[2 * p][0]     = r[0]; Bv[2 * p][1]     = r[2];
                Bv[2 * p + 1][0] = r[1]; Bv[2 * p + 1][1] = r[3];
            }
            #pragma unroll
            for (int mf = 0; mf < 4; ++mf)
                #pragma unroll
                for (int nf = 0; nf < 4; ++nf)
                    mma_16816(acc[mf][nf], A[mf], Bv[nf][0], Bv[nf][1]);
        }

        if (i + STAGES - 1 < KITERS)
            load_stage((i + STAGES - 1) & (STAGES - 1), (i + STAGES - 1) * BK);
        CP_COMMIT();
    }

    // epilogue: f = 2g + parity;  ri = cls>>1;  RE adds E512[b][t]
    const int par = cls & 1;
    const int ri  = cls >> 1;
    const int t_base = m0 + warp_m * 64 + (lane >> 2);
    const int g_base = n0 + warp_n * 32 + 2 * (lane & 3);
    const float* e512 = g_E512 + (size_t)b * N_FRAMES;
    float* ob = out + (size_t)b * F_BINS * N_FRAMES * 2 + ri;

    #pragma unroll
    for (int mf = 0; mf < 4; ++mf) {
        const int t0 = t_base + mf * 16;
        const float a0 = (cls == 0) ? e512[t0]     : 0.f;
        const float a1 = (cls == 0) ? e512[t0 + 8] : 0.f;
        #pragma unroll
        for (int nf = 0; nf < 4; ++nf) {
            const int g0 = g_base + nf * 8;
            const int f0 = 2 * g0 + par;
            const int f1 = f0 + 2;
            float* p0 = ob + ((size_t)f0 * N_FRAMES + t0) * 2;
            float* p1 = ob + ((size_t)f1 * N_FRAMES + t0) * 2;
            p0[0]  = acc[mf][nf][0] + a0;
            p1[0]  = acc[mf][nf][1] + a0;
            p0[16] = acc[mf][nf][2] + a1;   // t0+8
            p1[16] = acc[mf][nf][3] + a1;
        }
    }
}

// ---------------------------------------------------------------------------
// Host launcher
// ---------------------------------------------------------------------------
extern "C" void kernel_launch(void* const* d_in, const int* in_sizes, int n_in,
                              void* d_out, int out_size) {
    (void)in_sizes; (void)n_in; (void)out_size;
    const float* signal = (const float*)d_in[0];   // [16, 262144] fp32
    float* out = (float*)d_out;                    // [16, 513, 1025, 2] fp32

    // Prologue: double-fold frames + analytic kernel matrices
    fold_kernel<<<dim3(65, BATCH), 256>>>(signal);
    ker_build_kernel<<<(KF2 * KF2 + 255) / 256, 256>>>();

    // Main GEMMs: 4 classes x 16 batches, each 1024 x 256 x 256
    static bool attr_set = false;
    if (!attr_set) {
        cudaFuncSetAttribute(stft_gemm,
                             cudaFuncAttributeMaxDynamicSharedMemorySize,
                             SMEM_TOTAL);
        attr_set = true;
    }
    stft_gemm<<<dim3(2, 8, 64), 256, SMEM_TOTAL>>>(out);

    // Edges from folded data (t=1024 all f; f=512 t<1024)
    edge_last_frame<<<(BATCH * F_BINS + 7) / 8, 256>>>(out);
    edge_last_bin<<<BATCH * 1024 / 8, 256>>>(out);
}

// round 6
// speedup vs baseline: 3.4289x; 1.0253x over previous
#include <cuda_runtime.h>
#include <cuda_fp16.h>
#include <cstdint>

// ---------------------------------------------------------------------------
// Problem constants
// ---------------------------------------------------------------------------
#define SIG_LEN     262144
#define NFFT        1024
#define HOP         256
#define PADV        512
#define BATCH       16
#define F_BINS      513
#define N_FRAMES    1025
#define KF2         256            // twice-folded K

// GEMM tiling: CTA = 64(t) x 128(g), dual GEMM (real+imag)
#define BM 64
#define BN 128
#define BK 32
#define KITERS (KF2 / BK)          // 8
#define STAGES 3

#define AB_STRIDE 40               // halves per smem row (32 + 8 pad)
// stage rows: AR[0..63] AI[64..127] KC[128..255] KS[256..383]
#define STAGE_ROWS  384
#define STAGE_BYTES (STAGE_ROWS * AB_STRIDE * 2)   // 30720
#define SMEM_TOTAL  (STAGES * STAGE_BYTES)         // 92160

// fold kernel staging
#define FOLD_FRAMES 32
#define FOLD_SPAN   (FOLD_FRAMES * HOP + NFFT)     // 9216 floats

// ---------------------------------------------------------------------------
// Device scratch.  Classes: 0=RE (real,even f), 1=RO (real,odd), 2=IE, 3=IO
// ---------------------------------------------------------------------------
__device__ __half g_A[4][BATCH * N_FRAMES * KF2];  // frames per class [b][t][s]
__device__ __half g_K[4][KF2 * KF2];               // kernels per class [g][s]
__device__ float  g_E512[BATCH * N_FRAMES];        // y[512] per (b,t)

// ---------------------------------------------------------------------------
// PTX helpers (sm_100-safe)
// ---------------------------------------------------------------------------
__device__ __forceinline__ uint32_t smem_to_u32(const void* p) {
    uint32_t a;
    asm("{ .reg .u64 t; cvta.to.shared.u64 t, %1; cvt.u32.u64 %0, t; }"
        : "=r"(a) : "l"(p));
    return a;
}
__device__ __forceinline__ void cp_async16(uint32_t dst, const void* src) {
    asm volatile("cp.async.cg.shared.global [%0], [%1], 16;" :: "r"(dst), "l"(src));
}
#define CP_COMMIT() asm volatile("cp.async.commit_group;" ::: "memory")
#define CP_WAIT(N)  asm volatile("cp.async.wait_group %0;" :: "n"(N) : "memory")

__device__ __forceinline__ void ldmatrix_x4(uint32_t* r, uint32_t addr) {
    asm volatile("ldmatrix.sync.aligned.m8n8.x4.shared.b16 {%0,%1,%2,%3}, [%4];"
                 : "=r"(r[0]), "=r"(r[1]), "=r"(r[2]), "=r"(r[3]) : "r"(addr));
}
__device__ __forceinline__ void mma_16816(float* c, const uint32_t* a,
                                          uint32_t b0, uint32_t b1) {
    asm volatile(
        "mma.sync.aligned.m16n8k16.row.col.f32.f16.f16.f32 "
        "{%0,%1,%2,%3}, {%4,%5,%6,%7}, {%8,%9}, {%0,%1,%2,%3};"
        : "+f"(c[0]), "+f"(c[1]), "+f"(c[2]), "+f"(c[3])
        : "r"(a[0]), "r"(a[1]), "r"(a[2]), "r"(a[3]), "r"(b0), "r"(b1));
}

__device__ __forceinline__ int reflect_idx(int j) {   // padded coord -> signal idx
    int idx = j - PADV;
    idx = (idx < 0) ? -idx : idx;
    idx = (idx >= SIG_LEN) ? (2 * SIG_LEN - 2 - idx) : idx;
    return idx;
}

// ---------------------------------------------------------------------------
// Fused prologue.
//   blockIdx.x < 33 : fold frames (32 per block; chunk 32 = frame 1024 only)
//   blockIdx.x == 33: build analytic kernel matrices (16 y-slices)
//
// Fold math (validated round 5):
//   y[k] = x[k]*w[k];  E[j]=y[j]+y[1024-j], O[j]=y[j]-y[1024-j]; E[512]=y[512]
//   slot s (j=s+1, s<255): RE=E[j]+E[512-j], RO=E[j]-E[512-j],
//                          IE=O[j]-O[512-j], IO=O[j]+O[512-j]
//   slot 255: RE=E[256], RO=E[512], IE=0, IO=O[256]
// Kernel matrices (g,s; j=s+1):
//   K0=cos(pi g j/256), K1=cos(pi(2g+1)j/512) [slot255=-1],
//   K2=-sin(pi g j/256), K3=-sin(pi(2g+1)j/512)
// ---------------------------------------------------------------------------
__global__ void __launch_bounds__(256) fold_kernel(const float* __restrict__ sig) {
    if (blockIdx.x == 33) {            // kernel-matrix builder slice
        const int i0 = blockIdx.y * 4096 + threadIdx.x * 16;
        #pragma unroll
        for (int v = 0; v < 16; ++v) {
            const int i = i0 + v;
            const int g = i >> 8, ss = i & 255;
            const float j = (float)(ss + 1);
            const float ge = (float)g * j * (1.0f / 256.0f);
            const float go = (float)(2 * g + 1) * j * (1.0f / 512.0f);
            g_K[0][i] = __float2half(cospif(ge));
            g_K[1][i] = __float2half((ss < 255) ? cospif(go) : -1.0f);
            g_K[2][i] = __float2half(-sinpif(ge));
            g_K[3][i] = __float2half(-sinpif(go));
        }
        return;
    }

    __shared__ float s[FOLD_SPAN];
    __shared__ float wv[257];
    const int tid = threadIdx.x;
    const int b = blockIdx.y;
    const int t0 = blockIdx.x * FOLD_FRAMES;
    const int base = t0 * HOP;
    const float* sg = sig + (size_t)b * SIG_LEN;

    #pragma unroll 4
    for (int i = tid; i < FOLD_SPAN; i += 256)
        s[i] = sg[reflect_idx(base + i)];
    for (int i = tid; i <= 256; i += 256)
        wv[i] = 0.5f - 0.5f * cospif((float)i / 512.0f);
    __syncthreads();

    const int warp = tid >> 5, lane = tid & 31;
    const int nfr = (t0 == 1024) ? 1 : FOLD_FRAMES;
    for (int lt = warp; lt < nfr; lt += 8) {
        const int t = t0 + lt;
        const float* sf = s + lt * HOP;
        const size_t ro = ((size_t)b * N_FRAMES + t) * KF2;
        __half2* RE = reinterpret_cast<__half2*>(g_A[0] + ro);
        __half2* RO = reinterpret_cast<__half2*>(g_A[1] + ro);
        __half2* IE = reinterpret_cast<__half2*>(g_A[2] + ro);
        __half2* IO = reinterpret_cast<__half2*>(g_A[3] + ro);
        if (lane == 0)
            g_E512[b * N_FRAMES + t] = sf[512];   // w[512] = 1
        #pragma unroll
        for (int qq = 0; qq < 4; ++qq) {
            const int m = lane + qq * 32;          // half2 index: slots 2m, 2m+1
            float re[2], rr[2], ie[2], io[2];
            #pragma unroll
            for (int u = 0; u < 2; ++u) {
                const int ss = 2 * m + u;
                const int j = ss + 1;              // 1..256
                const float wj = wv[j];
                const float wc = 1.0f - wj;
                const float yj  = sf[j]        * wj;
                const float ymj = sf[1024 - j] * wj;
                const float ya  = sf[512 - j]  * wc;
                const float yb  = sf[512 + j]  * wc;
                const float uu = yj + ymj, vv = yj - ymj;
                const float pp = ya + yb,  q2 = ya - yb;
                re[u] = uu + pp;  rr[u] = uu - pp;
                ie[u] = vv - q2;  io[u] = vv + q2;
                if (ss == 255) {
                    re[u] = uu;                    // E[256]
                    rr[u] = sf[512];               // E[512]
                    io[u] = vv;                    // O[256]
                    ie[u] = 0.f;
                }
            }
            RE[m] = __floats2half2_rn(re[0], re[1]);
            RO[m] = __floats2half2_rn(rr[0], rr[1]);
            IE[m] = __floats2half2_rn(ie[0], ie[1]);
            IO[m] = __floats2half2_rn(io[0], io[1]);
        }
    }
}

// ---------------------------------------------------------------------------
// Merged edge kernel.
//   blockIdx.x < 1026  : frame t=1024, one warp per (b,f), f=0..512
//   blockIdx.x >= 1026 : bin f=512, t<1024, one warp per (b,t)
// ---------------------------------------------------------------------------
__global__ void __launch_bounds__(256) edge_kernel(float* __restrict__ out) {
    const int lane = threadIdx.x & 31;
    if (blockIdx.x < 1026) {
        const int gw = blockIdx.x * 8 + (threadIdx.x >> 5);
        if (gw >= BATCH * F_BINS) return;
        const int b = gw / F_BINS, f = gw - b * F_BINS;
        const size_t ro = ((size_t)b * N_FRAMES + 1024) * KF2;
        float ar = 0.f, ai = 0.f;
        if (f == 512) {
            const __half2* A = reinterpret_cast<const __half2*>(g_A[0] + ro);
            #pragma unroll
            for (int q = 0; q < 4; ++q) {
                float2 a = __half22float2(A[lane + q * 32]);
                ar += a.y - a.x;                 // sign (-1)^(s+1)
            }
        } else {
            const int p = f & 1, g = f >> 1;
            const __half2* Ar = reinterpret_cast<const __half2*>(g_A[p] + ro);
            const __half2* Kr = reinterpret_cast<const __half2*>(g_K[p] + (size_t)g * KF2);
            const __half2* Ai = reinterpret_cast<const __half2*>(g_A[2 + p] + ro);
            const __half2* Ki = reinterpret_cast<const __half2*>(g_K[2 + p] + (size_t)g * KF2);
            #pragma unroll
            for (int q = 0; q < 4; ++q) {
                const int m = lane + q * 32;
                float2 a = __half22float2(Ar[m]), k = __half22float2(Kr[m]);
                float2 c = __half22float2(Ai[m]), d = __half22float2(Ki[m]);
                ar += a.x * k.x + a.y * k.y;
                ai += c.x * d.x + c.y * d.y;
            }
        }
        #pragma unroll
        for (int off = 16; off; off >>= 1) {
            ar += __shfl_xor_sync(0xffffffffu, ar, off);
            ai += __shfl_xor_sync(0xffffffffu, ai, off);
        }
        if (lane == 0) {
            if ((f & 1) == 0) ar += g_E512[b * N_FRAMES + 1024];
            if (f == 512) ai = 0.f;
            float* op = out + (((size_t)b * F_BINS + f) * N_FRAMES + 1024) * 2;
            op[0] = ar;
            op[1] = ai;
        }
    } else {
        const int gw = (blockIdx.x - 1026) * 8 + (threadIdx.x >> 5);
        if (gw >= BATCH * 1024) return;
        const int b = gw >> 10, t = gw & 1023;
        const __half2* A = reinterpret_cast<const __half2*>(
            g_A[0] + ((size_t)b * N_FRAMES + t) * KF2);
        float ar = 0.f;
        #pragma unroll
        for (int q = 0; q < 4; ++q) {
            float2 a = __half22float2(A[lane + q * 32]);
            ar += a.y - a.x;
        }
        #pragma unroll
        for (int off = 16; off; off >>= 1)
            ar += __shfl_xor_sync(0xffffffffu, ar, off);
        if (lane == 0) {
            float* op = out + (((size_t)b * F_BINS + 512) * N_FRAMES + t) * 2;
            op[0] = ar + g_E512[b * N_FRAMES + t];
            op[1] = 0.f;
        }
    }
}

// ---------------------------------------------------------------------------
// Main GEMM: dual (real+imag) per CTA for one parity p.
//   real[t][g] = sum_s A[p][t][s]   * K[p][g][s]
//   imag[t][g] = sum_s A[2+p][t][s] * K[2+p][g][s]
//   f = 2g + p; out[b][f][t] = {real (+E512 if p==0), imag}  (float2 store)
//   grid = (2 g-tiles, 16 t-tiles, 32 = p*16+b), block = 256 (2x4 warps)
//   warp tile 32(t) x 32(g) per GEMM
// ---------------------------------------------------------------------------
__global__ void __launch_bounds__(256, 2) stft_gemm(float* __restrict__ out) {
    extern __shared__ __half smem[];
    const uint32_t sb = smem_to_u32(smem);
    const int tid = threadIdx.x;
    const int wid = tid >> 5;
    const int lane = tid & 31;
    const int n0 = blockIdx.x * BN;           // g-range start
    const int m0 = blockIdx.y * BM;           // t-range start
    const int b  = blockIdx.z & 15;
    const int p  = blockIdx.z >> 4;           // parity

    const __half* pAR = g_A[p]     + (size_t)b * N_FRAMES * KF2;
    const __half* pAI = g_A[2 + p] + (size_t)b * N_FRAMES * KF2;
    const __half* pKC = g_K[p];
    const __half* pKS = g_K[2 + p];

    // cp.async: 1536 16B-chunks per stage, 6 per thread; fixed (row, col)
    const __half* srcb[6];
    uint32_t dsto[6];
    #pragma unroll
    for (int k = 0; k < 6; ++k) {
        const int q = tid + k * 256;
        const int r = q >> 2, c = q & 3;
        dsto[k] = (r * AB_STRIDE + c * 8) * 2;
        const __half* bp;
        if      (r < 64)  bp = pAR + (size_t)(m0 + r) * KF2;
        else if (r < 128) bp = pAI + (size_t)(m0 + r - 64) * KF2;
        else if (r < 256) bp = pKC + (size_t)(n0 + r - 128) * KF2;
        else              bp = pKS + (size_t)(n0 + r - 256) * KF2;
        srcb[k] = bp + c * 8;
    }

    const int lm   = lane >> 3;
    const int l7   = lane & 7;
    const int row8 = (lm & 1) * 8 + l7;
    const int off8 = (lm >> 1) * 8;

    const int warp_m = wid & 1;               // 2 warps over t (32 each)
    const int warp_n = wid >> 1;              // 4 warps over g (32 each)

    float accR[2][4][4], accI[2][4][4];
    #pragma unroll
    for (int i = 0; i < 2; ++i)
        #pragma unroll
        for (int j = 0; j < 4; ++j)
            #pragma unroll
            for (int v = 0; v < 4; ++v) { accR[i][j][v] = 0.f; accI[i][j][v] = 0.f; }

    auto load_stage = [&](int s, int k0) {
        const uint32_t d = sb + s * STAGE_BYTES;
        #pragma unroll
        for (int k = 0; k < 6; ++k)
            cp_async16(d + dsto[k], srcb[k] + k0);
    };

    load_stage(0, 0);  CP_COMMIT();
    load_stage(1, BK); CP_COMMIT();

    int s = 0, ps = 2;
    for (int i = 0; i < KITERS; ++i) {
        CP_WAIT(STAGES - 2);
        __syncthreads();

        const uint32_t st = sb + s * STAGE_BYTES;

        #pragma unroll
        for (int ks = 0; ks < BK; ks += 16) {
            uint32_t AR[2][4], AI[2][4];
            #pragma unroll
            for (int mf = 0; mf < 2; ++mf) {
                const int row = warp_m * 32 + mf * 16 + row8;
                ldmatrix_x4(AR[mf], st + (row * AB_STRIDE + ks + off8) * 2);
                ldmatrix_x4(AI[mf], st + ((row + 64) * AB_STRIDE + ks + off8) * 2);
            }
            uint32_t BC[4][2], BS[4][2];
            #pragma unroll
            for (int ph = 0; ph < 2; ++ph) {
                const int nrow = warp_n * 32 + ph * 16 + row8;
                uint32_t r[4];
                ldmatrix_x4(r, st + ((nrow + 128) * AB_STRIDE + ks + off8) * 2);
                BC[2 * ph][0]     = r[0]; BC[2 * ph][1]     = r[2];
                BC[2 * ph + 1][0] = r[1]; BC[2 * ph + 1][1] = r[3];
                ldmatrix_x4(r, st + ((nrow + 256) * AB_STRIDE + ks + off8) * 2);
                BS[2 * ph][0]     = r[0]; BS[2 * ph][1]     = r[2];
                BS[2 * ph + 1][0] = r[1]; BS[2 * ph + 1][1] = r[3];
            }
            #pragma unroll
            for (int mf = 0; mf < 2; ++mf)
                #pragma unroll
                for (int nf = 0; nf < 4; ++nf) {
                    mma_16816(accR[mf][nf], AR[mf], BC[nf][0], BC[nf][1]);
                    mma_16816(accI[mf][nf], AI[mf], BS[nf][0], BS[nf][1]);
                }
        }

        if (i + 2 < KITERS)
            load_stage(ps, (i + 2) * BK);
        CP_COMMIT();
        s  = (s  == 2) ? 0 : s + 1;
        ps = (ps == 2) ? 0 : ps + 1;
    }

    // epilogue: float2 {real, imag} at out[b][f=2g+p][t]
    const int t_base = m0 + warp_m * 32 + (lane >> 2);
    const int g_base = n0 + warp_n * 32 + 2 * (lane & 3);
    const float* e512 = g_E512 + (size_t)b * N_FRAMES;
    float2* ob = reinterpret_cast<float2*>(out) + (size_t)b * F_BINS * N_FRAMES;

    #pragma unroll
    for (int mf = 0; mf < 2; ++mf) {
        const int t0 = t_base + mf * 16;
        const float a0 = (p == 0) ? e512[t0]     : 0.f;
        const float a1 = (p == 0) ? e512[t0 + 8] : 0.f;
        #pragma unroll
        for (int nf = 0; nf < 4; ++nf) {
            const int g0 = g_base + nf * 8;
            const int f0 = 2 * g0 + p;
            const int f1 = f0 + 2;
            float2* p0 = ob + (size_t)f0 * N_FRAMES + t0;
            float2* p1 = ob + (size_t)f1 * N_FRAMES + t0;
            p0[0] = make_float2(accR[mf][nf][0] + a0, accI[mf][nf][0]);
            p1[0] = make_float2(accR[mf][nf][1] + a0, accI[mf][nf][1]);
            p0[8] = make_float2(accR[mf][nf][2] + a1, accI[mf][nf][2]);
            p1[8] = make_float2(accR[mf][nf][3] + a1, accI[mf][nf][3]);
        }
    }
}

// ---------------------------------------------------------------------------
// Host launcher
// ---------------------------------------------------------------------------
extern "C" void kernel_launch(void* const* d_in, const int* in_sizes, int n_in,
                              void* d_out, int out_size) {
    (void)in_sizes; (void)n_in; (void)out_size;
    const float* signal = (const float*)d_in[0];   // [16, 262144] fp32
    float* out = (float*)d_out;                    // [16, 513, 1025, 2] fp32

    // Fused prologue: fold frames + build kernel matrices
    fold_kernel<<<dim3(34, BATCH), 256>>>(signal);

    // Main GEMMs: 2 parities x 16 batches, dual real/imag per CTA
    static bool attr_set = false;
    if (!attr_set) {
        cudaFuncSetAttribute(stft_gemm,
                             cudaFuncAttributeMaxDynamicSharedMemorySize,
                             SMEM_TOTAL);
        attr_set = true;
    }
    stft_gemm<<<dim3(2, 16, 32), 256, SMEM_TOTAL>>>(out);

    // Edges (t=1024 all f; f=512 t<1024) in one launch
    edge_kernel<<<1026 + 2048, 256>>>(out);
}